// round 3
// baseline (speedup 1.0000x reference)
#include <cuda_runtime.h>
#include <cuda_bf16.h>
#include <cstdint>

// ============================================================================
// QuantizedLinear: y[M,N] = x[M,K] @ Wq[N,K]^T * scale + bias
// M=16384, N=4096, K=4096.
// sm_103 base-ISA path (harness PTX target has no 'a' suffix -> no tcgen05):
//   - exact bf16 split of x (hi+lo), exact bf16 weights (ints < 128)
//   - mma.sync m16n8k16 bf16 HMMA, fp32 register accumulators
//   - cp.async.bulk + mbarrier 3-stage pipeline, pre-swizzled global tiles
// R3 fix: K-step advance inside a SW128-swizzled tile is XOR, not ADD.
// ============================================================================

#define M_TOTAL  16384
#define N_TOTAL  4096
#define K_TOTAL  4096

#define TILE_M   128
#define TILE_N   128
#define TILE_K   64          // 64 bf16 = 128 bytes/row = SW128 atom width
#define NUM_KT   (K_TOTAL / TILE_K)   // 64
#define STAGES   3

#define A_TILE_BYTES  (TILE_M * TILE_K * 2)   // 16384
#define B_TILE_BYTES  (TILE_N * TILE_K * 2)   // 16384
#define STAGE_BYTES   (2 * A_TILE_BYTES + B_TILE_BYTES)  // 49152

#define TILES_M  (M_TOTAL / TILE_M)   // 128
#define TILES_N  (N_TOTAL / TILE_N)   // 32

// Scratch: pre-tiled, pre-swizzled operands (static device arrays, no allocs).
__device__ uint4 g_xhi[(size_t)M_TOTAL * K_TOTAL / 8];   // 128 MB bf16
__device__ uint4 g_xlo[(size_t)M_TOTAL * K_TOTAL / 8];   // 128 MB bf16
__device__ uint4 g_wbf[(size_t)N_TOTAL * K_TOTAL / 8];   //  32 MB bf16

// ---------------------------------------------------------------------------
// PTX helpers (base ISA only)
// ---------------------------------------------------------------------------
__device__ __forceinline__ uint32_t smem_u32(const void* p) {
    uint32_t a;
    asm("{ .reg .u64 t; cvta.to.shared.u64 t, %1; cvt.u32.u64 %0, t; }"
        : "=r"(a) : "l"(p));
    return a;
}
__device__ __forceinline__ void mbar_init(uint32_t mbar, uint32_t count) {
    asm volatile("mbarrier.init.shared.b64 [%0], %1;" :: "r"(mbar), "r"(count) : "memory");
}
__device__ __forceinline__ void mbar_expect_tx(uint32_t mbar, uint32_t bytes) {
    asm volatile("mbarrier.arrive.expect_tx.shared.b64 _, [%0], %1;"
                 :: "r"(mbar), "r"(bytes) : "memory");
}
__device__ __forceinline__ void mbar_arrive(uint32_t mbar) {
    asm volatile("mbarrier.arrive.shared.b64 _, [%0];" :: "r"(mbar) : "memory");
}
__device__ __forceinline__ void mbar_wait(uint32_t mbar, uint32_t parity) {
    asm volatile(
        "{\n\t.reg .pred P;\n\t"
        "WAITLOOP_%=:\n\t"
        "mbarrier.try_wait.parity.acquire.cta.shared::cta.b64 P, [%0], %1, 0x989680;\n\t"
        "@!P bra WAITLOOP_%=;\n\t}"
        :: "r"(mbar), "r"(parity) : "memory");
}
__device__ __forceinline__ void bulk_g2s(uint32_t dst, const void* src,
                                         uint32_t bytes, uint32_t mbar) {
    asm volatile(
        "cp.async.bulk.shared::cta.global.mbarrier::complete_tx::bytes [%0], [%1], %2, [%3];"
        :: "r"(dst), "l"(src), "r"(bytes), "r"(mbar) : "memory");
}
#define FENCE_PROXY_ASYNC() asm volatile("fence.proxy.async;" ::: "memory")

__device__ __forceinline__ void ldsm_x4(uint32_t* r, uint32_t addr) {
    asm volatile("ldmatrix.sync.aligned.m8n8.x4.shared.b16 {%0,%1,%2,%3}, [%4];"
                 : "=r"(r[0]), "=r"(r[1]), "=r"(r[2]), "=r"(r[3]) : "r"(addr));
}
__device__ __forceinline__ void mma16816(float* c, const uint32_t* a, const uint32_t* b) {
    asm volatile(
        "mma.sync.aligned.m16n8k16.row.col.f32.bf16.bf16.f32 "
        "{%0,%1,%2,%3}, {%4,%5,%6,%7}, {%8,%9}, {%0,%1,%2,%3};"
        : "+f"(c[0]), "+f"(c[1]), "+f"(c[2]), "+f"(c[3])
        : "r"(a[0]), "r"(a[1]), "r"(a[2]), "r"(a[3]), "r"(b[0]), "r"(b[1]));
}

__device__ __forceinline__ uint32_t sw128(uint32_t off) {
    return off ^ ((off >> 3) & 0x70);
}
__device__ __forceinline__ uint32_t pack_bf2(__nv_bfloat16 a, __nv_bfloat16 b) {
    return (uint32_t)__bfloat16_as_ushort(a) | ((uint32_t)__bfloat16_as_ushort(b) << 16);
}

// ---------------------------------------------------------------------------
// Prep 1: split x (fp32) -> x_hi, x_lo (bf16), tiled [mt][kt][128x64] SW128.
// ---------------------------------------------------------------------------
__global__ void __launch_bounds__(256) split_x_kernel(const float* __restrict__ x) {
    uint32_t gid = blockIdx.x * 256u + threadIdx.x;   // M*K/8 threads
    int m  = gid >> 9;
    int k  = (gid & 511) << 3;

    const float4* xp = reinterpret_cast<const float4*>(x + ((size_t)m << 12) + k);
    float4 a = xp[0], b = xp[1];
    float f[8] = {a.x, a.y, a.z, a.w, b.x, b.y, b.z, b.w};

    uint32_t hi[4], lo[4];
#pragma unroll
    for (int i = 0; i < 4; i++) {
        __nv_bfloat16 h0 = __float2bfloat16(f[2*i]);
        __nv_bfloat16 h1 = __float2bfloat16(f[2*i+1]);
        __nv_bfloat16 l0 = __float2bfloat16(f[2*i]   - __bfloat162float(h0));
        __nv_bfloat16 l1 = __float2bfloat16(f[2*i+1] - __bfloat162float(h1));
        hi[i] = pack_bf2(h0, h1);
        lo[i] = pack_bf2(l0, l1);
    }

    int mt = m >> 7, row = m & 127, kt = k >> 6, kin = k & 63;
    size_t base = ((size_t)(mt * NUM_KT + kt)) * A_TILE_BYTES;
    uint32_t off = sw128((uint32_t)(row * 128 + kin * 2));

    *reinterpret_cast<uint4*>(reinterpret_cast<char*>(g_xhi) + base + off) =
        make_uint4(hi[0], hi[1], hi[2], hi[3]);
    *reinterpret_cast<uint4*>(reinterpret_cast<char*>(g_xlo) + base + off) =
        make_uint4(lo[0], lo[1], lo[2], lo[3]);
}

// ---------------------------------------------------------------------------
// Prep 2: weight int32 -> bf16 (exact), tiled [nt][kt][128x64] SW128.
// ---------------------------------------------------------------------------
__global__ void __launch_bounds__(256) conv_w_kernel(const int* __restrict__ wq) {
    uint32_t gid = blockIdx.x * 256u + threadIdx.x;   // N*K/8 threads
    int n = gid >> 9;
    int k = (gid & 511) << 3;

    const int4* wp = reinterpret_cast<const int4*>(wq + ((size_t)n << 12) + k);
    int4 a = wp[0], b = wp[1];
    int v[8] = {a.x, a.y, a.z, a.w, b.x, b.y, b.z, b.w};

    uint32_t w[4];
#pragma unroll
    for (int i = 0; i < 4; i++) {
        w[i] = pack_bf2(__float2bfloat16((float)v[2*i]),
                        __float2bfloat16((float)v[2*i+1]));
    }

    int nt = n >> 7, row = n & 127, kt = k >> 6, kin = k & 63;
    size_t base = ((size_t)(nt * NUM_KT + kt)) * B_TILE_BYTES;
    uint32_t off = sw128((uint32_t)(row * 128 + kin * 2));

    *reinterpret_cast<uint4*>(reinterpret_cast<char*>(g_wbf) + base + off) =
        make_uint4(w[0], w[1], w[2], w[3]);
}

// ---------------------------------------------------------------------------
// GEMM: 128x128 output tile per CTA. 8 consumer warps (32x64 each, 4Mx2N),
// 1 producer warp. 3-stage bulk-copy pipeline.
// ---------------------------------------------------------------------------
#define NTHREADS      288                       // 8 consumer warps + 1 producer
#define SMEM_RAW_BYTES (1024 + 1024 + STAGES * STAGE_BYTES)

__global__ void __launch_bounds__(NTHREADS, 1)
gemm_kernel(float* __restrict__ out, const float* __restrict__ scale,
            const float* __restrict__ bias) {
    extern __shared__ char smem_raw[];
    uint32_t sb = (smem_u32(smem_raw) + 1023u) & ~1023u;

    const int tid = threadIdx.x;
    const int wid = tid >> 5;
    const int lid = tid & 31;

    // L2-friendly tile grouping: 4 m-tiles x 32 n-tiles per group of 128 CTAs
    int bid = blockIdx.x;
    int grp = bid >> 7;
    int r   = bid & 127;
    int mt  = (grp << 2) + (r & 3);
    int nt  = r >> 2;

    const uint32_t FULL_BAR  = sb;          // 3 x 8B
    const uint32_t EMPTY_BAR = sb + 32;     // 3 x 8B
    const uint32_t DATA      = sb + 1024;

    if (tid == 0) {
#pragma unroll
        for (int s = 0; s < STAGES; s++) {
            mbar_init(FULL_BAR  + s * 8, 1);   // producer's expect_tx arrive
            mbar_init(EMPTY_BAR + s * 8, 8);   // 8 consumer warps
        }
        FENCE_PROXY_ASYNC();
    }
    __syncthreads();

    // ---------------- Producer warp ----------------
    if (wid == 8) {
        if (lid == 0) {
            const char* xhi = reinterpret_cast<const char*>(g_xhi) +
                              (size_t)mt * NUM_KT * A_TILE_BYTES;
            const char* xlo = reinterpret_cast<const char*>(g_xlo) +
                              (size_t)mt * NUM_KT * A_TILE_BYTES;
            const char* wbf = reinterpret_cast<const char*>(g_wbf) +
                              (size_t)nt * NUM_KT * B_TILE_BYTES;

            auto issue = [&](int s, int kt) {
                uint32_t fb = FULL_BAR + s * 8;
                uint32_t d  = DATA + s * STAGE_BYTES;
                mbar_expect_tx(fb, STAGE_BYTES);
                bulk_g2s(d,                    xhi + (size_t)kt * A_TILE_BYTES, A_TILE_BYTES, fb);
                bulk_g2s(d + A_TILE_BYTES,     xlo + (size_t)kt * A_TILE_BYTES, A_TILE_BYTES, fb);
                bulk_g2s(d + 2 * A_TILE_BYTES, wbf + (size_t)kt * B_TILE_BYTES, B_TILE_BYTES, fb);
            };

            issue(0, 0); issue(1, 1); issue(2, 2);
            int ep[STAGES] = {0, 0, 0};
            for (int kt = STAGES; kt < NUM_KT; kt++) {
                int s = kt % STAGES;
                mbar_wait(EMPTY_BAR + s * 8, ep[s]); ep[s] ^= 1;
                issue(s, kt);
            }
        }
        return;   // producer warp done (no __syncthreads below)
    }

    // ---------------- Consumer warps ----------------
    const int warp_m = wid & 3;          // 4 warps over M: 32 rows each
    const int warp_n = wid >> 2;         // 2 warps over N: 64 cols each

    // Per-lane swizzled SMEM offsets (ks=0). K advance inside the swizzled
    // tile is XOR with ks*32 (bits 5-6; unswizzled base has them clear).
    uint32_t a_off[2], b_off[4];
#pragma unroll
    for (int mf = 0; mf < 2; mf++) {
        int row = warp_m * 32 + mf * 16 + (lid & 15);
        a_off[mf] = sw128((uint32_t)(row * 128 + (lid >> 4) * 16));
    }
#pragma unroll
    for (int nfp = 0; nfp < 4; nfp++) {
        int nrow = warp_n * 64 + nfp * 16 + (lid & 7) + ((lid >> 4) & 1) * 8;
        b_off[nfp] = sw128((uint32_t)(nrow * 128 + ((lid >> 3) & 1) * 16));
    }

    float acc[2][8][4];
#pragma unroll
    for (int mf = 0; mf < 2; mf++)
#pragma unroll
        for (int nf = 0; nf < 8; nf++)
#pragma unroll
            for (int i = 0; i < 4; i++) acc[mf][nf][i] = 0.f;

    int fp[STAGES] = {0, 0, 0};

#pragma unroll 1
    for (int kt = 0; kt < NUM_KT; kt++) {
        int s = kt % STAGES;
        mbar_wait(FULL_BAR + s * 8, fp[s]); fp[s] ^= 1;

        uint32_t ah = DATA + s * STAGE_BYTES;
        uint32_t al = ah + A_TILE_BYTES;
        uint32_t bb = al + A_TILE_BYTES;

#pragma unroll
        for (int ks = 0; ks < 4; ks++) {
            uint32_t kb = ks * 32;      // XOR into swizzled offset (bits 5-6)
            uint32_t ahi[2][4], alo[2][4], bfr[4][4];
            ldsm_x4(ahi[0], ah + (a_off[0] ^ kb));
            ldsm_x4(ahi[1], ah + (a_off[1] ^ kb));
            ldsm_x4(alo[0], al + (a_off[0] ^ kb));
            ldsm_x4(alo[1], al + (a_off[1] ^ kb));
            ldsm_x4(bfr[0], bb + (b_off[0] ^ kb));
            ldsm_x4(bfr[1], bb + (b_off[1] ^ kb));
            ldsm_x4(bfr[2], bb + (b_off[2] ^ kb));
            ldsm_x4(bfr[3], bb + (b_off[3] ^ kb));

#pragma unroll
            for (int mf = 0; mf < 2; mf++)
#pragma unroll
                for (int nf = 0; nf < 8; nf++) {
                    const uint32_t* bp = &bfr[nf >> 1][(nf & 1) * 2];
                    mma16816(acc[mf][nf], ahi[mf], bp);
                    mma16816(acc[mf][nf], alo[mf], bp);
                }
        }

        __syncwarp();
        if (lid == 0) mbar_arrive(EMPTY_BAR + s * 8);
    }

    // ---------------- Epilogue: y = scale * acc + bias ----------------
    float scl = __ldg(scale);
    int row0 = (mt << 7) + warp_m * 32 + (lid >> 2);
    int col0 = (nt << 7) + warp_n * 64 + (lid & 3) * 2;

#pragma unroll
    for (int nf = 0; nf < 8; nf++) {
        int col = col0 + nf * 8;
        float2 bv = __ldg(reinterpret_cast<const float2*>(bias + col));
#pragma unroll
        for (int mf = 0; mf < 2; mf++) {
            int ra = row0 + mf * 16;
            float2 o0, o1;
            o0.x = scl * acc[mf][nf][0] + bv.x;
            o0.y = scl * acc[mf][nf][1] + bv.y;
            o1.x = scl * acc[mf][nf][2] + bv.x;
            o1.y = scl * acc[mf][nf][3] + bv.y;
            *reinterpret_cast<float2*>(out + ((size_t)ra << 12)       + col) = o0;
            *reinterpret_cast<float2*>(out + ((size_t)(ra + 8) << 12) + col) = o1;
        }
    }
}

// ---------------------------------------------------------------------------
// Launch
// ---------------------------------------------------------------------------
extern "C" void kernel_launch(void* const* d_in, const int* in_sizes, int n_in,
                              void* d_out, int out_size) {
    const float* x     = (const float*)d_in[0];   // [4,4096,4096] fp32
    const int*   wq    = (const int*)  d_in[1];   // [4096,4096]   int32
    const float* scale = (const float*)d_in[2];   // [1]           fp32
    const float* bias  = (const float*)d_in[3];   // [4096]        fp32
    float*       out   = (float*)d_out;           // [4,4096,4096] fp32

    split_x_kernel<<<(M_TOTAL * (K_TOTAL / 8)) / 256, 256>>>(x);
    conv_w_kernel <<<(N_TOTAL * (K_TOTAL / 8)) / 256, 256>>>(wq);

    cudaFuncSetAttribute(gemm_kernel, cudaFuncAttributeMaxDynamicSharedMemorySize,
                         SMEM_RAW_BYTES);
    gemm_kernel<<<TILES_M * TILES_N, NTHREADS, SMEM_RAW_BYTES>>>(out, scale, bias);
}